// round 2
// baseline (speedup 1.0000x reference)
#include <cuda_runtime.h>
#include <math.h>

// S4D kernel generation:
//   K[h,l] = 2 * Re( sum_n C_scaled[h,n] * exp(dtA[h,n] * l) )
// Strategy: per-lane geometric recurrence y *= exp(32*dtA), 2 modes packed
// per f32x2 register pair, updated with packed mul/fma PTX (FFMA2).
// R1 change: SEGS 2 -> 4 to fill the register-capped 12 blocks/SM; unroll 4.

#define NHALF_C 32
#define NPAIR   16
#define SEGS    4

typedef unsigned long long u64;

#define F2MUL(d,a,b)    asm("mul.rn.f32x2 %0, %1, %2;"     : "=l"(d) : "l"(a), "l"(b))
#define F2FMA(d,a,b,c)  asm("fma.rn.f32x2 %0, %1, %2, %3;" : "=l"(d) : "l"(a), "l"(b), "l"(c))
#define F2ADD(d,a,b)    asm("add.rn.f32x2 %0, %1, %2;"     : "=l"(d) : "l"(a), "l"(b))
#define F2PACK(d,lo,hi) asm("mov.b64 %0, {%1, %2};"        : "=l"(d) : "f"(lo), "f"(hi))
#define F2UNPK(lo,hi,s) asm("mov.b64 {%0, %1}, %2;"        : "=f"(lo), "=f"(hi) : "l"(s))

// Range-reduce x (double) into [-pi, pi], return float residue.
__device__ __forceinline__ float red2pi(double x) {
    const double TWO_PI     = 6.283185307179586476925286766559;
    const double INV_TWO_PI = 0.15915494309189533576888376337251;
    double k = rint(x * INV_TWO_PI);
    return (float)__fma_rn(k, -TWO_PI, x);
}

__global__ void __launch_bounds__(32)
s4d_kernel(const float* __restrict__ C,
           const float* __restrict__ log_dt,
           const float* __restrict__ log_A_real,
           const float* __restrict__ A_imag,
           float* __restrict__ K,
           int H, int L, int iters)
{
    const int blk  = blockIdx.x;
    const int h    = blk / SEGS;
    const int seg  = blk % SEGS;
    const int lane = threadIdx.x;
    if (h >= H) return;

    const int seg_len = L / SEGS;
    const int l0 = seg * seg_len + lane;

    // dt via double exp so --use_fast_math can't degrade it (phase-critical).
    const float dt = (float)exp((double)log_dt[h]);

    u64 yr[NPAIR], yi[NPAIR], wr[NPAIR], wi[NPAIR], nwi[NPAIR];

    #pragma unroll
    for (int p = 0; p < NPAIR; ++p) {
        float yrv[2], yiv[2], wrv[2], wiv[2];
        #pragma unroll
        for (int k = 0; k < 2; ++k) {
            const int n   = 2 * p + k;
            const int idx = h * NHALF_C + n;
            const float arl = log_A_real[idx];
            const float av  = A_imag[idx];
            const float c0  = C[2 * idx + 0];
            const float c1  = C[2 * idx + 1];

            const float are = (float)exp((double)arl);   // exp(log_A_real)
            const float dre = -dt * are;                 // Re(dtA)
            const float dim =  dt * av;                  // Im(dtA)

            // w1 = exp(dtA); C_scaled = 2 * (C) * (w1 - 1) / A, A = (-are, av)
            const float e1 = __expf(dre);
            float s1, co1; __sincosf(dim, &s1, &co1);
            const float numr = __fmaf_rn(e1, co1, -1.0f);
            const float numi = e1 * s1;
            const float tr = c0 * numr - c1 * numi;
            const float ti = c0 * numi + c1 * numr;
            const float inv = 2.0f / (are * are + av * av);
            const float csr = (ti * av - tr * are) * inv;
            const float csi = -(ti * are + tr * av) * inv;

            // y0 = C_scaled * exp(dtA * l0); phase reduced in double
            const float mag = __expf(dre * (float)l0);
            const float ph  = red2pi((double)dim * (double)l0);
            float sp, cp; __sincosf(ph, &sp, &cp);
            const float er = mag * cp, ei = mag * sp;
            yrv[k] = csr * er - csi * ei;
            yiv[k] = csr * ei + csi * er;

            // per-iter multiplier: wstep = exp(32 * dtA)
            const float m32 = __expf(dre * 32.0f);
            const float p32 = red2pi((double)dim * 32.0);
            float s32, c32; __sincosf(p32, &s32, &c32);
            wrv[k] = m32 * c32;
            wiv[k] = m32 * s32;
        }
        F2PACK(yr[p],  yrv[0],  yrv[1]);
        F2PACK(yi[p],  yiv[0],  yiv[1]);
        F2PACK(wr[p],  wrv[0],  wrv[1]);
        F2PACK(wi[p],  wiv[0],  wiv[1]);
        F2PACK(nwi[p], -wiv[0], -wiv[1]);
    }

    float* out = K + (size_t)h * L + l0;

    #pragma unroll 4
    for (int it = 0; it < iters; ++it) {
        // ---- reduce current Re(y) across the 16 pairs (packed tree) ----
        u64 t[8];
        #pragma unroll
        for (int j = 0; j < 8; ++j) F2ADD(t[j], yr[2 * j], yr[2 * j + 1]);
        #pragma unroll
        for (int j = 0; j < 4; ++j) F2ADD(t[j], t[2 * j], t[2 * j + 1]);
        #pragma unroll
        for (int j = 0; j < 2; ++j) F2ADD(t[j], t[2 * j], t[2 * j + 1]);
        F2ADD(t[0], t[0], t[1]);

        // ---- advance the recurrence: y *= wstep (uses pre-update yr) ----
        #pragma unroll
        for (int p = 0; p < NPAIR; ++p) {
            u64 m0, m1;
            F2MUL(m0, yi[p], nwi[p]);      // -yi*wi
            F2MUL(m1, yr[p], wi[p]);       //  yr*wi (old yr)
            F2FMA(yr[p], yr[p], wr[p], m0);
            F2FMA(yi[p], yi[p], wr[p], m1);
        }

        float a, b; F2UNPK(a, b, t[0]);
        *out = a + b;                       // coalesced 128B/warp store
        out += 32;
    }
}

extern "C" void kernel_launch(void* const* d_in, const int* in_sizes, int n_in,
                              void* d_out, int out_size) {
    const float* C          = (const float*)d_in[0];
    const float* log_dt     = (const float*)d_in[1];
    const float* log_A_real = (const float*)d_in[2];
    const float* A_imag     = (const float*)d_in[3];

    const int H = in_sizes[1];           // log_dt has H elements
    const int L = out_size / H;          // K is (H, L)
    const int iters = L / (SEGS * 32);

    s4d_kernel<<<H * SEGS, 32>>>(C, log_dt, log_A_real, A_imag,
                                 (float*)d_out, H, L, iters);
}

// round 3
// speedup vs baseline: 1.0913x; 1.0913x over previous
#include <cuda_runtime.h>
#include <math.h>

// S4D kernel generation:
//   K[h,l] = 2 * Re( sum_n C_scaled[h,n] * exp(dtA[h,n] * l) )
// Per-lane geometric recurrence y *= exp(32*dtA), 2 modes packed per f32x2
// register pair (FFMA2 via PTX).
// R3: 32 modes split across 2 warps (8 pairs each) -> ~100 regs, no spills,
//     ~5 resident warps/SMSP. Cross-warp combine via double-buffered smem.

#define NHALF_C 32
#define NPAIR   8      // pairs per warp (16 modes per warp, 2 warps)
#define SEGS    4

typedef unsigned long long u64;

#define F2MUL(d,a,b)    asm("mul.rn.f32x2 %0, %1, %2;"     : "=l"(d) : "l"(a), "l"(b))
#define F2FMA(d,a,b,c)  asm("fma.rn.f32x2 %0, %1, %2, %3;" : "=l"(d) : "l"(a), "l"(b), "l"(c))
#define F2ADD(d,a,b)    asm("add.rn.f32x2 %0, %1, %2;"     : "=l"(d) : "l"(a), "l"(b))
#define F2PACK(d,lo,hi) asm("mov.b64 %0, {%1, %2};"        : "=l"(d) : "f"(lo), "f"(hi))
#define F2UNPK(lo,hi,s) asm("mov.b64 {%0, %1}, %2;"        : "=f"(lo), "=f"(hi) : "l"(s))

// Range-reduce x (double) into [-pi, pi], return float residue.
__device__ __forceinline__ float red2pi(double x) {
    const double TWO_PI     = 6.283185307179586476925286766559;
    const double INV_TWO_PI = 0.15915494309189533576888376337251;
    double k = rint(x * INV_TWO_PI);
    return (float)__fma_rn(k, -TWO_PI, x);
}

__global__ void __launch_bounds__(64)
s4d_kernel(const float* __restrict__ C,
           const float* __restrict__ log_dt,
           const float* __restrict__ log_A_real,
           const float* __restrict__ A_imag,
           float* __restrict__ K,
           int H, int L, int iters)
{
    __shared__ float buf[2][32];

    const int blk  = blockIdx.x;
    const int h    = blk / SEGS;
    const int seg  = blk % SEGS;
    const int lane = threadIdx.x & 31;
    const int warp = threadIdx.x >> 5;    // 0 or 1; warp w owns modes [16w,16w+16)
    if (h >= H) return;

    const int seg_len = L / SEGS;
    const int l0 = seg * seg_len + lane;

    // dt via double exp so --use_fast_math can't degrade it (phase-critical).
    const float dt = (float)exp((double)log_dt[h]);

    u64 yr[NPAIR], yi[NPAIR], wr[NPAIR], wi[NPAIR], nwi[NPAIR];

    #pragma unroll
    for (int p = 0; p < NPAIR; ++p) {
        float yrv[2], yiv[2], wrv[2], wiv[2];
        #pragma unroll
        for (int k = 0; k < 2; ++k) {
            const int n   = warp * 16 + 2 * p + k;
            const int idx = h * NHALF_C + n;
            const float arl = log_A_real[idx];
            const float av  = A_imag[idx];
            const float c0  = C[2 * idx + 0];
            const float c1  = C[2 * idx + 1];

            const float are = (float)exp((double)arl);   // exp(log_A_real)
            const float dre = -dt * are;                 // Re(dtA)
            const float dim =  dt * av;                  // Im(dtA)

            // w1 = exp(dtA); C_scaled = 2 * C * (w1 - 1) / A, A = (-are, av)
            const float e1 = __expf(dre);
            float s1, co1; __sincosf(dim, &s1, &co1);
            const float numr = __fmaf_rn(e1, co1, -1.0f);
            const float numi = e1 * s1;
            const float tr = c0 * numr - c1 * numi;
            const float ti = c0 * numi + c1 * numr;
            const float inv = 2.0f / (are * are + av * av);
            const float csr = (ti * av - tr * are) * inv;
            const float csi = -(ti * are + tr * av) * inv;

            // y0 = C_scaled * exp(dtA * l0); phase reduced in double
            const float mag = __expf(dre * (float)l0);
            const float ph  = red2pi((double)dim * (double)l0);
            float sp, cp; __sincosf(ph, &sp, &cp);
            const float er = mag * cp, ei = mag * sp;
            yrv[k] = csr * er - csi * ei;
            yiv[k] = csr * ei + csi * er;

            // per-iter multiplier: wstep = exp(32 * dtA)
            const float m32 = __expf(dre * 32.0f);
            const float p32 = red2pi((double)dim * 32.0);
            float s32, c32; __sincosf(p32, &s32, &c32);
            wrv[k] = m32 * c32;
            wiv[k] = m32 * s32;
        }
        F2PACK(yr[p],  yrv[0],  yrv[1]);
        F2PACK(yi[p],  yiv[0],  yiv[1]);
        F2PACK(wr[p],  wrv[0],  wrv[1]);
        F2PACK(wi[p],  wiv[0],  wiv[1]);
        F2PACK(nwi[p], -wiv[0], -wiv[1]);
    }

    float* out = K + (size_t)h * L + l0;

    #pragma unroll 2
    for (int it = 0; it < iters; ++it) {
        // ---- reduce current Re(y) over this warp's 8 pairs (packed tree) ----
        u64 t[4];
        #pragma unroll
        for (int j = 0; j < 4; ++j) F2ADD(t[j], yr[2 * j], yr[2 * j + 1]);
        F2ADD(t[0], t[0], t[1]);
        F2ADD(t[2], t[2], t[3]);
        F2ADD(t[0], t[0], t[2]);
        float a, b; F2UNPK(a, b, t[0]);
        const float part = a + b;

        if (warp == 1) buf[it & 1][lane] = part;

        // ---- advance the recurrence (independent of smem traffic) ----
        #pragma unroll
        for (int p = 0; p < NPAIR; ++p) {
            u64 m0, m1;
            F2MUL(m0, yi[p], nwi[p]);      // -yi*wi
            F2MUL(m1, yr[p], wi[p]);       //  yr*wi (old yr)
            F2FMA(yr[p], yr[p], wr[p], m0);
            F2FMA(yi[p], yi[p], wr[p], m1);
        }

        __syncthreads();

        if (warp == 0) {
            out[0] = part + buf[it & 1][lane];   // coalesced 128B/warp store
            out += 32;
        }
    }
}

extern "C" void kernel_launch(void* const* d_in, const int* in_sizes, int n_in,
                              void* d_out, int out_size) {
    const float* C          = (const float*)d_in[0];
    const float* log_dt     = (const float*)d_in[1];
    const float* log_A_real = (const float*)d_in[2];
    const float* A_imag     = (const float*)d_in[3];

    const int H = in_sizes[1];           // log_dt has H elements
    const int L = out_size / H;          // K is (H, L)
    const int iters = L / (SEGS * 32);

    s4d_kernel<<<H * SEGS, 64>>>(C, log_dt, log_A_real, A_imag,
                                 (float*)d_out, H, L, iters);
}

// round 4
// speedup vs baseline: 1.7091x; 1.5662x over previous
#include <cuda_runtime.h>
#include <math.h>

// S4D kernel generation:
//   K[h,l] = 2 * Re( sum_n C_scaled[h,n] * exp(dtA[h,n] * l) )
// Per-lane geometric recurrence y *= exp(32*dtA), 2 modes packed per f32x2
// register pair (FFMA2 via PTX), 32 modes per thread, one warp per (h,seg).
// R4: SEGS=4 + __launch_bounds__(32,12) -> 12 warps/SM at 170 regs, no
//     spills (R1 body, unroll 2), no cross-warp barrier. Init cheapened
//     (expf for the decay exp; doubles only for dt and phase reduction).

#define NHALF_C 32
#define NPAIR   16
#define SEGS    4

typedef unsigned long long u64;

#define F2MUL(d,a,b)    asm("mul.rn.f32x2 %0, %1, %2;"     : "=l"(d) : "l"(a), "l"(b))
#define F2FMA(d,a,b,c)  asm("fma.rn.f32x2 %0, %1, %2, %3;" : "=l"(d) : "l"(a), "l"(b), "l"(c))
#define F2ADD(d,a,b)    asm("add.rn.f32x2 %0, %1, %2;"     : "=l"(d) : "l"(a), "l"(b))
#define F2PACK(d,lo,hi) asm("mov.b64 %0, {%1, %2};"        : "=l"(d) : "f"(lo), "f"(hi))
#define F2UNPK(lo,hi,s) asm("mov.b64 {%0, %1}, %2;"        : "=f"(lo), "=f"(hi) : "l"(s))

// Range-reduce x (double) into [-pi, pi], return float residue.
__device__ __forceinline__ float red2pi(double x) {
    const double TWO_PI     = 6.283185307179586476925286766559;
    const double INV_TWO_PI = 0.15915494309189533576888376337251;
    double k = rint(x * INV_TWO_PI);
    return (float)__fma_rn(k, -TWO_PI, x);
}

__global__ void __launch_bounds__(32, 12)
s4d_kernel(const float* __restrict__ C,
           const float* __restrict__ log_dt,
           const float* __restrict__ log_A_real,
           const float* __restrict__ A_imag,
           float* __restrict__ K,
           int H, int L, int iters)
{
    const int blk  = blockIdx.x;
    const int h    = blk / SEGS;
    const int seg  = blk % SEGS;
    const int lane = threadIdx.x;

    const int seg_len = L / SEGS;
    const int l0 = seg * seg_len + lane;

    // dt via double exp (once) so --use_fast_math can't degrade it.
    const float dt = (float)exp((double)log_dt[h]);

    u64 yr[NPAIR], yi[NPAIR], wr[NPAIR], wi[NPAIR], nwi[NPAIR];

    #pragma unroll
    for (int p = 0; p < NPAIR; ++p) {
        float yrv[2], yiv[2], wrv[2], wiv[2];
        #pragma unroll
        for (int k = 0; k < 2; ++k) {
            const int n   = 2 * p + k;
            const int idx = h * NHALF_C + n;
            const float arl = log_A_real[idx];
            const float av  = A_imag[idx];
            const float c0  = C[2 * idx + 0];
            const float c1  = C[2 * idx + 1];

            const float are = __expf(arl);               // exp(log_A_real): decay only
            const float dre = -dt * are;                 // Re(dtA)
            const float dim =  dt * av;                  // Im(dtA)

            // w1 = exp(dtA); C_scaled = 2 * C * (w1 - 1) / A, A = (-are, av)
            const float e1 = __expf(dre);
            float s1, co1; __sincosf(dim, &s1, &co1);
            const float numr = __fmaf_rn(e1, co1, -1.0f);
            const float numi = e1 * s1;
            const float tr = c0 * numr - c1 * numi;
            const float ti = c0 * numi + c1 * numr;
            const float inv = 2.0f / (are * are + av * av);
            const float csr = (ti * av - tr * are) * inv;
            const float csi = -(ti * are + tr * av) * inv;

            // y0 = C_scaled * exp(dtA * l0); phase reduced in double
            const float mag = __expf(dre * (float)l0);
            const float ph  = red2pi((double)dim * (double)l0);
            float sp, cp; __sincosf(ph, &sp, &cp);
            const float er = mag * cp, ei = mag * sp;
            yrv[k] = csr * er - csi * ei;
            yiv[k] = csr * ei + csi * er;

            // per-iter multiplier: wstep = exp(32 * dtA)
            const float m32 = __expf(dre * 32.0f);
            const float p32 = red2pi((double)dim * 32.0);
            float s32, c32; __sincosf(p32, &s32, &c32);
            wrv[k] = m32 * c32;
            wiv[k] = m32 * s32;
        }
        F2PACK(yr[p],  yrv[0],  yrv[1]);
        F2PACK(yi[p],  yiv[0],  yiv[1]);
        F2PACK(wr[p],  wrv[0],  wrv[1]);
        F2PACK(wi[p],  wiv[0],  wiv[1]);
        F2PACK(nwi[p], -wiv[0], -wiv[1]);
    }

    float* out = K + (size_t)h * L + l0;

    #pragma unroll 2
    for (int it = 0; it < iters; ++it) {
        // ---- reduce current Re(y) across the 16 pairs (packed tree) ----
        u64 t[8];
        #pragma unroll
        for (int j = 0; j < 8; ++j) F2ADD(t[j], yr[2 * j], yr[2 * j + 1]);
        #pragma unroll
        for (int j = 0; j < 4; ++j) F2ADD(t[j], t[2 * j], t[2 * j + 1]);
        #pragma unroll
        for (int j = 0; j < 2; ++j) F2ADD(t[j], t[2 * j], t[2 * j + 1]);
        F2ADD(t[0], t[0], t[1]);

        // ---- advance the recurrence: y *= wstep (uses pre-update yr) ----
        #pragma unroll
        for (int p = 0; p < NPAIR; ++p) {
            u64 m0, m1;
            F2MUL(m0, yi[p], nwi[p]);      // -yi*wi
            F2MUL(m1, yr[p], wi[p]);       //  yr*wi (old yr)
            F2FMA(yr[p], yr[p], wr[p], m0);
            F2FMA(yi[p], yi[p], wr[p], m1);
        }

        float a, b; F2UNPK(a, b, t[0]);
        *out = a + b;                       // coalesced 128B/warp store
        out += 32;
    }
}

extern "C" void kernel_launch(void* const* d_in, const int* in_sizes, int n_in,
                              void* d_out, int out_size) {
    const float* C          = (const float*)d_in[0];
    const float* log_dt     = (const float*)d_in[1];
    const float* log_A_real = (const float*)d_in[2];
    const float* A_imag     = (const float*)d_in[3];

    const int H = in_sizes[1];           // log_dt has H elements
    const int L = out_size / H;          // K is (H, L)
    const int iters = L / (SEGS * 32);

    s4d_kernel<<<H * SEGS, 32>>>(C, log_dt, log_A_real, A_imag,
                                 (float*)d_out, H, L, iters);
}